// round 15
// baseline (speedup 1.0000x reference)
#include <cuda_runtime.h>
#include <cuda_bf16.h>
#include <mma.h>
#include <math.h>
#include <stdint.h>

using namespace nvcuda;

#define Pn 7
#define Sn 4
#define SCALE 0.0625f
#define TRANS_STD 0.1f
#define Cc 128
#define DF 1024
#define Bb 2
#define Hh 160
#define Ww 160
#define Nroi 256
#define INF (Cc*Pn*Pn)   // 6272
#define HW (Hh*Ww)       // 25600

// ---------------- scratch ----------------
__device__ float g_dataT[Bb*HW*Cc];                 // (B,H,W,C)
__device__ __align__(16) __nv_bfloat16 g_xh[Nroi*INF];
__device__ __align__(16) __nv_bfloat16 g_xl[Nroi*INF];
__device__ __align__(16) __nv_bfloat16 g_W1h[(size_t)INF*2*DF];  // [6272][2048] = w1 | wm1 (hi), k-major
__device__ __align__(16) __nv_bfloat16 g_W1l[(size_t)INF*2*DF];  // lo
__device__ __align__(16) __nv_bfloat16 g_W2h[DF*DF];             // w2 [1024][1024] (hi)
__device__ __align__(16) __nv_bfloat16 g_W2l[DF*DF];             // lo
__device__ float g_part[11010048];                  // partials (21*256*2048)
__device__ __align__(16) __nv_bfloat16 g_h1h[Nroi*DF];
__device__ __align__(16) __nv_bfloat16 g_h1l[Nroi*DF];
__device__ float g_m1[Nroi*DF];
__device__ float g_h2[Nroi*DF];
__device__ float g_off[Nroi*2*Pn*Pn];
__device__ float g_mask[Nroi*Pn*Pn];

__device__ __forceinline__ uint32_t smem_u32(const void* p) {
    uint32_t a;
    asm("{ .reg .u64 t; cvta.to.shared.u64 t, %1; cvt.u32.u64 %0, t; }" : "=r"(a) : "l"(p));
    return a;
}

// ---------------- transpose (B,C,H,W) -> (B,H,W,C) ----------------
__global__ void transpose_kernel(const float* __restrict__ in) {
    __shared__ float tile[32][33];
    int b  = blockIdx.z;
    int p0 = blockIdx.x * 32;
    int c0 = blockIdx.y * 32;
    int tx = threadIdx.x, ty = threadIdx.y;
    const float* src = in + (size_t)b * Cc * HW;
    float* dst = g_dataT + (size_t)b * HW * Cc;
    #pragma unroll
    for (int i = 0; i < 4; i++)
        tile[ty + 8*i][tx] = src[(c0 + ty + 8*i) * HW + p0 + tx];
    __syncthreads();
    #pragma unroll
    for (int i = 0; i < 4; i++)
        dst[(p0 + ty + 8*i) * Cc + c0 + tx] = tile[tx][ty + 8*i];
}

// ---------------- streaming weight convert + bf16 hi/lo split (NO transpose) ----
// w layouts stay [K][ncols=1024], n contiguous. z=1 selects w_b -> column offset 1024.
__global__ void convW_kernel(const float* __restrict__ w_a, const float* __restrict__ w_b,
                             __nv_bfloat16* __restrict__ Wh,
                             __nv_bfloat16* __restrict__ Wl,
                             int total4, int ldt, int two) {
    const float* w = (two && blockIdx.z) ? w_b : w_a;
    int nOff = (two && blockIdx.z) ? DF : 0;
    int i = blockIdx.x * 256 + threadIdx.x;
    if (i >= total4) return;
    int e = i * 4;
    int k = e >> 10;          // /1024
    int n = e & 1023;
    float4 v = *(const float4*)(w + e);
    __nv_bfloat16 h0 = __float2bfloat16(v.x);
    __nv_bfloat16 h1 = __float2bfloat16(v.y);
    __nv_bfloat16 h2 = __float2bfloat16(v.z);
    __nv_bfloat16 h3 = __float2bfloat16(v.w);
    __nv_bfloat16 l0 = __float2bfloat16(v.x - __bfloat162float(h0));
    __nv_bfloat16 l1 = __float2bfloat16(v.y - __bfloat162float(h1));
    __nv_bfloat16 l2 = __float2bfloat16(v.z - __bfloat162float(h2));
    __nv_bfloat16 l3 = __float2bfloat16(v.w - __bfloat162float(h3));
    size_t o = (size_t)k * ldt + nOff + n;
    __nv_bfloat162 hv0; hv0.x = h0; hv0.y = h1;
    __nv_bfloat162 hv1; hv1.x = h2; hv1.y = h3;
    __nv_bfloat162 lv0; lv0.x = l0; lv0.y = l1;
    __nv_bfloat162 lv1; lv1.x = l2; lv1.y = l3;
    ((__nv_bfloat162*)(Wh + o))[0] = hv0;
    ((__nv_bfloat162*)(Wh + o))[1] = hv1;
    ((__nv_bfloat162*)(Wl + o))[0] = lv0;
    ((__nv_bfloat162*)(Wl + o))[1] = lv1;
}

// ---------------- deformable RoI pool (two-phase hybrid) ----------------
template<bool TRANS>
__global__ __launch_bounds__(128) void pool_kernel(
    const float* __restrict__ rois,
    const float* __restrict__ trans,
    const float* __restrict__ mask,
    float* __restrict__ out)
{
    __shared__ int4   s_o[Pn*16];
    __shared__ float4 s_w[Pn*16];
    __shared__ int    s_cnt[Pn];
    __shared__ int    s_base;

    int n  = blockIdx.x;
    int ph = blockIdx.y;
    int tid = threadIdx.x;

    if (tid < Pn) s_cnt[tid] = 0;
    __syncthreads();

    if (tid < Pn * 16) {
        int pw = tid >> 4;
        int s  = tid & 15;
        int ih = s >> 2;
        int iw = s & 3;

        const float* r = rois + n * 5;
        int   bi = (int)r[0];
        float x1 = rintf(r[1]) * SCALE - 0.5f;
        float y1 = rintf(r[2]) * SCALE - 0.5f;
        float x2 = (rintf(r[3]) + 1.0f) * SCALE - 0.5f;
        float y2 = (rintf(r[4]) + 1.0f) * SCALE - 0.5f;
        float roi_w = fmaxf(x2 - x1, 0.1f);
        float roi_h = fmaxf(y2 - y1, 0.1f);
        float bin_w = roi_w / (float)Pn;
        float bin_h = roi_h / (float)Pn;
        float sub_w = bin_w / (float)Sn;
        float sub_h = bin_h / (float)Sn;

        float tx = 0.f, tyv = 0.f;
        if (TRANS) {
            tx  = trans[n*98 +      ph*7 + pw] * TRANS_STD;
            tyv = trans[n*98 + 49 + ph*7 + pw] * TRANS_STD;
        }
        float wv = (float)pw * bin_w + x1 + tx  * roi_w + (float)iw * sub_w;
        float hv = (float)ph * bin_h + y1 + tyv * roi_h + (float)ih * sub_h;

        int4   o4 = make_int4(0, 0, 0, 0);
        float4 w4 = make_float4(0.f, 0.f, 0.f, 0.f);
        bool valid = !(wv < -0.5f || wv > (float)Ww - 0.5f ||
                       hv < -0.5f || hv > (float)Hh - 0.5f);
        if (valid) {
            float wc = fminf(fmaxf(wv, 0.f), (float)Ww - 1.f);
            float hc = fminf(fmaxf(hv, 0.f), (float)Hh - 1.f);
            int x0 = (int)floorf(wc);
            int y0 = (int)floorf(hc);
            int x1i = min(x0 + 1, Ww - 1);
            int y1i = min(y0 + 1, Hh - 1);
            float lx = wc - (float)x0;
            float ly = hc - (float)y0;
            o4.x = (y0 * Ww + x0) * Cc;
            o4.y = (x1i - x0) * Cc;
            o4.z = (y1i - y0) * Ww * Cc;
            w4 = make_float4((1.f-ly)*(1.f-lx), (1.f-ly)*lx, ly*(1.f-lx), ly*lx);
            atomicAdd(&s_cnt[pw], 1);
        }
        s_o[tid] = o4;
        s_w[tid] = w4;
        if (tid == 0) s_base = bi * HW * Cc;
    }
    __syncthreads();

    int wid = tid >> 5;
    int l   = tid & 31;
    const float* base = g_dataT + s_base;
    int c4 = l * 4;

    #pragma unroll
    for (int pp = 0; pp < 2; pp++) {
        int pw = wid + pp * 4;
        if (pw >= Pn) break;
        float4 acc = make_float4(0.f, 0.f, 0.f, 0.f);
        #pragma unroll 4
        for (int s = 0; s < 16; s++) {
            int4   o = s_o[pw*16 + s];
            float4 w = s_w[pw*16 + s];
            const float* p = base + o.x + c4;
            float4 v00 = *(const float4*)(p);
            float4 v01 = *(const float4*)(p + o.y);
            float4 v10 = *(const float4*)(p + o.z);
            float4 v11 = *(const float4*)(p + o.y + o.z);
            acc.x += v00.x*w.x + v01.x*w.y + v10.x*w.z + v11.x*w.w;
            acc.y += v00.y*w.x + v01.y*w.y + v10.y*w.z + v11.y*w.w;
            acc.z += v00.z*w.x + v01.z*w.y + v10.z*w.z + v11.z*w.w;
            acc.w += v00.w*w.x + v01.w*w.y + v10.w*w.z + v11.w*w.w;
        }
        int cnt = s_cnt[pw];
        float a[4] = {acc.x, acc.y, acc.z, acc.w};
        float mk = TRANS ? mask[n*49 + ph*7 + pw] : 0.f;
        #pragma unroll
        for (int j = 0; j < 4; j++) {
            float res = (cnt > 0) ? a[j] / (float)cnt : 0.f;
            int oidx = n*INF + (c4 + j)*49 + ph*7 + pw;
            if (TRANS) {
                out[oidx] = res * mk;
            } else {
                __nv_bfloat16 hi = __float2bfloat16(res);
                g_xh[oidx] = hi;
                g_xl[oidx] = __float2bfloat16(res - __bfloat162float(hi));
            }
        }
    }
}

// ---------------- WMMA bf16 GEMM, row-major B, cp.async 2-stage, KS=64 ----------
// C_tile[128x128] = A[128 x Kper] @ B[Kper x 128]   (B is [K][N], N contiguous)
// grid: x = Ntiles, y = Mtiles, z = term*kchunks + kc
//   term 0: Ah@Bh   term 1: Ah@Bl   term 2: Al@Bh
#define KS 64
#define SPAD_A 72
#define SPAD_B 136
#define NSTG 2
#define A_ELEMS (128 * SPAD_A)
#define B_ELEMS (KS * SPAD_B)
#define STG_ELEMS (A_ELEMS + B_ELEMS)
__global__ __launch_bounds__(256) void gemm_wmma(
    const __nv_bfloat16* __restrict__ Ah, const __nv_bfloat16* __restrict__ Al, int lda,
    const __nv_bfloat16* __restrict__ Bh, const __nv_bfloat16* __restrict__ Bl, int ldb,
    float* __restrict__ part, int Kper, int kchunks, int Nfull)
{
    extern __shared__ __nv_bfloat16 smem[];

    int tid = threadIdx.x;
    int wid = tid >> 5;
    int wm = wid & 3;       // 0..3 : M position (32 rows each)
    int wn = wid >> 2;      // 0..1 : N position (64 cols each)

    int z = blockIdx.z;
    int term = z / kchunks;
    int kc   = z % kchunks;
    const __nv_bfloat16* A = (term == 2) ? Al : Ah;
    const __nv_bfloat16* B = (term == 1) ? Bl : Bh;

    int m0 = blockIdx.y * 128;
    int n0 = blockIdx.x * 128;
    const __nv_bfloat16* Abase = A + (size_t)m0 * lda + (size_t)kc * Kper;
    const __nv_bfloat16* Bbase = B + (size_t)kc * Kper * ldb + n0;

    wmma::fragment<wmma::accumulator, 16, 16, 16, float> acc[2][4];
    #pragma unroll
    for (int i = 0; i < 2; i++)
        #pragma unroll
        for (int j = 0; j < 4; j++) wmma::fill_fragment(acc[i][j], 0.0f);

    int stages = Kper / KS;
    int rA  = tid >> 3;      // 0..31
    int cA  = tid & 7;       // 16B chunk in 128B A row

    auto issue = [&](int s) {
        int buf = s % NSTG;
        __nv_bfloat16* dA = smem + buf * STG_ELEMS;
        __nv_bfloat16* dB = dA + A_ELEMS;
        const __nv_bfloat16* a = Abase + s * KS;
        const __nv_bfloat16* b = Bbase + (size_t)s * KS * ldb;
        // A: 128 rows x 64 bf16 (128B) = 1024 chunks
        #pragma unroll
        for (int i = 0; i < 4; i++) {
            int rr = i * 32 + rA;
            uint32_t da = smem_u32(dA + rr * SPAD_A + cA * 8);
            asm volatile("cp.async.cg.shared.global [%0], [%1], 16;"
                         :: "r"(da), "l"(a + (size_t)rr * lda + cA * 8));
        }
        // B: 64 rows x 128 bf16 (256B) = 1024 chunks
        #pragma unroll
        for (int i = 0; i < 4; i++) {
            int idx = i * 256 + tid;
            int rr = idx >> 4;
            int ch = idx & 15;
            uint32_t db = smem_u32(dB + rr * SPAD_B + ch * 8);
            asm volatile("cp.async.cg.shared.global [%0], [%1], 16;"
                         :: "r"(db), "l"(b + (size_t)rr * ldb + ch * 8));
        }
        asm volatile("cp.async.commit_group;");
    };

    #pragma unroll
    for (int i = 0; i < NSTG - 1; i++) {
        if (i < stages) issue(i);
        else asm volatile("cp.async.commit_group;");
    }

    for (int s = 0; s < stages; s++) {
        if (s + NSTG - 1 < stages) issue(s + NSTG - 1);
        else asm volatile("cp.async.commit_group;");

        asm volatile("cp.async.wait_group %0;" :: "n"(NSTG - 1));
        __syncthreads();

        int buf = s % NSTG;
        const __nv_bfloat16* cAp = smem + buf * STG_ELEMS;
        const __nv_bfloat16* cBp = cAp + A_ELEMS;
        #pragma unroll
        for (int kk = 0; kk < KS; kk += 16) {
            wmma::fragment<wmma::matrix_a, 16, 16, 16, __nv_bfloat16, wmma::row_major> af[2];
            wmma::fragment<wmma::matrix_b, 16, 16, 16, __nv_bfloat16, wmma::row_major> bfr[4];
            #pragma unroll
            for (int i = 0; i < 2; i++)
                wmma::load_matrix_sync(af[i], cAp + (wm * 32 + i * 16) * SPAD_A + kk, SPAD_A);
            #pragma unroll
            for (int j = 0; j < 4; j++)
                wmma::load_matrix_sync(bfr[j], cBp + kk * SPAD_B + wn * 64 + j * 16, SPAD_B);
            #pragma unroll
            for (int i = 0; i < 2; i++)
                #pragma unroll
                for (int j = 0; j < 4; j++)
                    wmma::mma_sync(acc[i][j], af[i], bfr[j], acc[i][j]);
        }
        __syncthreads();
    }

    float* outp = part + ((size_t)z * Nroi + m0) * Nfull + n0;
    #pragma unroll
    for (int i = 0; i < 2; i++)
        #pragma unroll
        for (int j = 0; j < 4; j++)
            wmma::store_matrix_sync(outp + (size_t)(wm * 32 + i * 16) * Nfull + wn * 64 + j * 16,
                                    acc[i][j], Nfull, wmma::mem_row_major);
}

// ---------------- reduce 1: sum 21 slices [256][2048]; split h (bf16 hi/lo) / m (fp32)
__global__ void reduce1_kernel(const float* __restrict__ b1, const float* __restrict__ bm1) {
    int i = blockIdx.x * 256 + threadIdx.x;   // over 256*2048
    int m = i >> 11;
    int n = i & 2047;
    float s = (n < DF) ? b1[n] : bm1[n - DF];
    #pragma unroll
    for (int zz = 0; zz < 21; zz++) s += g_part[(size_t)zz * (Nroi*2*DF) + i];
    s = fmaxf(s, 0.f);
    if (n < DF) {
        __nv_bfloat16 hi = __float2bfloat16(s);
        g_h1h[m*DF + n] = hi;
        g_h1l[m*DF + n] = __float2bfloat16(s - __bfloat162float(hi));
    } else {
        g_m1[m*DF + n - DF] = s;
    }
}

// ---------------- reduce 2: sum 24 slices [256][1024] + b2, relu -> h2 fp32
__global__ void reduce2_kernel(const float* __restrict__ b2) {
    int i = blockIdx.x * 256 + threadIdx.x;
    int n = i & (DF - 1);
    float s = b2[n];
    #pragma unroll
    for (int zz = 0; zz < 24; zz++) s += g_part[(size_t)zz * (Nroi*DF) + i];
    g_h2[i] = fmaxf(s, 0.f);
}

// ---------------- small GEMM: (256,1024) @ (1024,Ncols) + bias [, sigmoid] -------
__global__ __launch_bounds__(128) void gemm_small(
    const float* __restrict__ A, const float* __restrict__ Wt,
    const float* __restrict__ bias, float* __restrict__ out,
    int Ncols, int act)
{
    __shared__ float arow[8][DF];
    int tid = threadIdx.x;
    int m0 = blockIdx.x * 8;
    #pragma unroll
    for (int g = 0; g < 8; g++)
        for (int k = tid; k < DF; k += 128)
            arow[g][k] = A[(size_t)(m0 + g) * DF + k];
    __syncthreads();

    if (tid < Ncols) {
        float bv = bias[tid];
        float acc[8];
        #pragma unroll
        for (int g = 0; g < 8; g++) acc[g] = bv;
        for (int k = 0; k < DF; k += 4) {
            float w0 = Wt[(size_t)(k + 0) * Ncols + tid];
            float w1 = Wt[(size_t)(k + 1) * Ncols + tid];
            float w2 = Wt[(size_t)(k + 2) * Ncols + tid];
            float w3 = Wt[(size_t)(k + 3) * Ncols + tid];
            #pragma unroll
            for (int g = 0; g < 8; g++) {
                float4 av = *(const float4*)&arow[g][k];
                acc[g] += av.x * w0 + av.y * w1 + av.z * w2 + av.w * w3;
            }
        }
        #pragma unroll
        for (int g = 0; g < 8; g++) {
            float v = acc[g];
            if (act) v = 1.f / (1.f + expf(-v));
            out[(size_t)(m0 + g) * Ncols + tid] = v;
        }
    }
}

// ---------------- launch ----------------
extern "C" void kernel_launch(void* const* d_in, const int* in_sizes, int n_in,
                              void* d_out, int out_size) {
    const float* data = (const float*)d_in[0];
    const float* rois = (const float*)d_in[1];
    const float* w1   = (const float*)d_in[2];
    const float* b1   = (const float*)d_in[3];
    const float* w2   = (const float*)d_in[4];
    const float* b2   = (const float*)d_in[5];
    const float* w3   = (const float*)d_in[6];
    const float* b3   = (const float*)d_in[7];
    const float* wm1  = (const float*)d_in[8];
    const float* bm1  = (const float*)d_in[9];
    const float* wm2  = (const float*)d_in[10];
    const float* bm2  = (const float*)d_in[11];
    float* out = (float*)d_out;

    float *p_part, *p_m1, *p_h2, *p_off, *p_mask;
    __nv_bfloat16 *p_xh, *p_xl, *p_W1h, *p_W1l, *p_W2h, *p_W2l, *p_h1h, *p_h1l;
    cudaGetSymbolAddress((void**)&p_part, g_part);
    cudaGetSymbolAddress((void**)&p_m1,   g_m1);
    cudaGetSymbolAddress((void**)&p_h2,   g_h2);
    cudaGetSymbolAddress((void**)&p_off,  g_off);
    cudaGetSymbolAddress((void**)&p_mask, g_mask);
    cudaGetSymbolAddress((void**)&p_xh,   g_xh);
    cudaGetSymbolAddress((void**)&p_xl,   g_xl);
    cudaGetSymbolAddress((void**)&p_W1h,  g_W1h);
    cudaGetSymbolAddress((void**)&p_W1l,  g_W1l);
    cudaGetSymbolAddress((void**)&p_W2h,  g_W2h);
    cudaGetSymbolAddress((void**)&p_W2l,  g_W2l);
    cudaGetSymbolAddress((void**)&p_h1h,  g_h1h);
    cudaGetSymbolAddress((void**)&p_h1l,  g_h1l);

    static int attr_set = 0;
    if (!attr_set) {
        cudaFuncSetAttribute(gemm_wmma, cudaFuncAttributeMaxDynamicSharedMemorySize,
                             NSTG * STG_ELEMS * 2);
        attr_set = 1;
    }
    const int smem_bytes = NSTG * STG_ELEMS * 2;   // 71680

    // idx 0: transpose data to channel-last
    transpose_kernel<<<dim3(HW/32, Cc/32, Bb), dim3(32, 8)>>>(data);

    // idx 1: streaming convert+split for w1 & wm1 -> [6272][2048]
    convW_kernel<<<dim3((INF*DF/4 + 255)/256, 1, 2), 256>>>(w1, wm1, p_W1h, p_W1l,
                                                            INF*DF/4, 2*DF, 1);

    // idx 2: pool1 -> xh/xl bf16
    pool_kernel<false><<<dim3(Nroi, Pn), 128>>>(rois, nullptr, nullptr, nullptr);

    // idx 3 (ncu capture slot): gemm1 [256x6272]@[6272x2048], 3 terms x splitK7 -> 21 slices
    gemm_wmma<<<dim3(16, 2, 21), 256, smem_bytes>>>(p_xh, p_xl, INF, p_W1h, p_W1l, 2*DF,
                                                    p_part, INF/7, 7, 2*DF);

    // idx 4: streaming convert+split for w2 -> [1024][1024]
    convW_kernel<<<dim3((DF*DF/4 + 255)/256, 1, 1), 256>>>(w2, nullptr, p_W2h, p_W2l,
                                                           DF*DF/4, DF, 0);

    // idx 5: reduce -> h1 (bf16 hi/lo) and m1 (fp32)
    reduce1_kernel<<<(Nroi*2*DF)/256, 256>>>(b1, bm1);

    // idx 6: gemm2 [256x1024]@[1024x1024], 3 terms x splitK8 -> 24 slices
    gemm_wmma<<<dim3(8, 2, 24), 256, smem_bytes>>>(p_h1h, p_h1l, DF, p_W2h, p_W2l, DF,
                                                   p_part, DF/8, 8, DF);

    // idx 7: reduce -> h2 fp32
    reduce2_kernel<<<(Nroi*DF)/256, 256>>>(b2);

    // idx 8/9: offsets & mask heads
    gemm_small<<<Nroi/8, 128>>>(p_h2, w3, b3, p_off, 2*Pn*Pn, 0);
    gemm_small<<<Nroi/8, 128>>>(p_m1, wm2, bm2, p_mask, Pn*Pn, 1);

    // idx 10: pool2 with offsets, multiply mask -> out
    pool_kernel<true><<<dim3(Nroi, Pn), 128>>>(rois, p_off, p_mask, out);
}

// round 16
// speedup vs baseline: 1.0450x; 1.0450x over previous
#include <cuda_runtime.h>
#include <cuda_bf16.h>
#include <mma.h>
#include <math.h>
#include <stdint.h>

using namespace nvcuda;

#define Pn 7
#define Sn 4
#define SCALE 0.0625f
#define TRANS_STD 0.1f
#define Cc 128
#define DF 1024
#define Bb 2
#define Hh 160
#define Ww 160
#define Nroi 256
#define INF (Cc*Pn*Pn)   // 6272
#define HW (Hh*Ww)       // 25600

// ---------------- scratch ----------------
__device__ float g_dataT[Bb*HW*Cc];                 // (B,H,W,C)
__device__ __align__(16) __nv_bfloat16 g_xh[Nroi*INF];
__device__ __align__(16) __nv_bfloat16 g_xl[Nroi*INF];
__device__ __align__(16) __nv_bfloat16 g_Wt1h[2*DF*INF];   // [2048][6272] = w1^T | wm1^T (hi)
__device__ __align__(16) __nv_bfloat16 g_Wt1l[2*DF*INF];   // lo
__device__ __align__(16) __nv_bfloat16 g_Wt2h[DF*DF];      // w2^T hi
__device__ __align__(16) __nv_bfloat16 g_Wt2l[DF*DF];      // w2^T lo
__device__ float g_part[11010048];                  // partials (21*256*2048)
__device__ __align__(16) __nv_bfloat16 g_h1h[Nroi*DF];
__device__ __align__(16) __nv_bfloat16 g_h1l[Nroi*DF];
__device__ float g_m1[Nroi*DF];
__device__ float g_h2[Nroi*DF];
__device__ float g_off[Nroi*2*Pn*Pn];
__device__ float g_mask[Nroi*Pn*Pn];

__device__ __forceinline__ uint32_t smem_u32(const void* p) {
    uint32_t a;
    asm("{ .reg .u64 t; cvta.to.shared.u64 t, %1; cvt.u32.u64 %0, t; }" : "=r"(a) : "l"(p));
    return a;
}

// ---------------- transpose (B,C,H,W) -> (B,H,W,C) ----------------
__global__ void transpose_kernel(const float* __restrict__ in) {
    __shared__ float tile[32][33];
    int b  = blockIdx.z;
    int p0 = blockIdx.x * 32;
    int c0 = blockIdx.y * 32;
    int tx = threadIdx.x, ty = threadIdx.y;
    const float* src = in + (size_t)b * Cc * HW;
    float* dst = g_dataT + (size_t)b * HW * Cc;
    #pragma unroll
    for (int i = 0; i < 4; i++)
        tile[ty + 8*i][tx] = src[(c0 + ty + 8*i) * HW + p0 + tx];
    __syncthreads();
    #pragma unroll
    for (int i = 0; i < 4; i++)
        dst[(p0 + ty + 8*i) * Cc + c0 + tx] = tile[tx][ty + 8*i];
}

// ---------------- weight transpose + bf16 hi/lo split (vectorized stores) -------
// src w: [K][DF] (n contiguous). Output Wt[nOff+n][k] with row length ldt.
// Each thread handles 1 output row x 4 consecutive k, stored as 2x bf16x2 (4B each).
__global__ __launch_bounds__(256) void transW_kernel(
    const float* __restrict__ w_a, const float* __restrict__ w_b,
    __nv_bfloat16* __restrict__ Wth, __nv_bfloat16* __restrict__ Wtl,
    int ldt, int two)
{
    __shared__ float tile[32][33];   // [k_local][n_local]
    const float* w = (two && blockIdx.z) ? w_b : w_a;
    int nOff = (two && blockIdx.z) ? DF : 0;
    int k0 = blockIdx.x * 32;
    int n0 = blockIdx.y * 32;
    int tid = threadIdx.x;
    int lk = tid >> 5;       // 0..7
    int ln = tid & 31;
    #pragma unroll
    for (int i = 0; i < 4; i++)
        tile[lk + 8*i][ln] = w[(size_t)(k0 + lk + 8*i) * DF + n0 + ln];
    __syncthreads();

    int nl = tid >> 3;       // 0..31 output row within tile
    int kc = tid & 7;        // 0..7, covers k-offsets kc*4..kc*4+3
    float v0 = tile[kc*4+0][nl];
    float v1 = tile[kc*4+1][nl];
    float v2 = tile[kc*4+2][nl];
    float v3 = tile[kc*4+3][nl];
    __nv_bfloat16 h0 = __float2bfloat16(v0);
    __nv_bfloat16 h1 = __float2bfloat16(v1);
    __nv_bfloat16 h2 = __float2bfloat16(v2);
    __nv_bfloat16 h3 = __float2bfloat16(v3);
    __nv_bfloat16 l0 = __float2bfloat16(v0 - __bfloat162float(h0));
    __nv_bfloat16 l1 = __float2bfloat16(v1 - __bfloat162float(h1));
    __nv_bfloat16 l2 = __float2bfloat16(v2 - __bfloat162float(h2));
    __nv_bfloat16 l3 = __float2bfloat16(v3 - __bfloat162float(h3));
    size_t o = (size_t)(nOff + n0 + nl) * ldt + k0 + kc * 4;
    __nv_bfloat162 ha; ha.x = h0; ha.y = h1;
    __nv_bfloat162 hb; hb.x = h2; hb.y = h3;
    __nv_bfloat162 la; la.x = l0; la.y = l1;
    __nv_bfloat162 lb; lb.x = l2; lb.y = l3;
    ((__nv_bfloat162*)(Wth + o))[0] = ha;
    ((__nv_bfloat162*)(Wth + o))[1] = hb;
    ((__nv_bfloat162*)(Wtl + o))[0] = la;
    ((__nv_bfloat162*)(Wtl + o))[1] = lb;
}

// ---------------- deformable RoI pool (two-phase hybrid) ----------------
template<bool TRANS>
__global__ __launch_bounds__(128) void pool_kernel(
    const float* __restrict__ rois,
    const float* __restrict__ trans,
    const float* __restrict__ mask,
    float* __restrict__ out)
{
    __shared__ int4   s_o[Pn*16];
    __shared__ float4 s_w[Pn*16];
    __shared__ int    s_cnt[Pn];
    __shared__ int    s_base;

    int n  = blockIdx.x;
    int ph = blockIdx.y;
    int tid = threadIdx.x;

    if (tid < Pn) s_cnt[tid] = 0;
    __syncthreads();

    if (tid < Pn * 16) {
        int pw = tid >> 4;
        int s  = tid & 15;
        int ih = s >> 2;
        int iw = s & 3;

        const float* r = rois + n * 5;
        int   bi = (int)r[0];
        float x1 = rintf(r[1]) * SCALE - 0.5f;
        float y1 = rintf(r[2]) * SCALE - 0.5f;
        float x2 = (rintf(r[3]) + 1.0f) * SCALE - 0.5f;
        float y2 = (rintf(r[4]) + 1.0f) * SCALE - 0.5f;
        float roi_w = fmaxf(x2 - x1, 0.1f);
        float roi_h = fmaxf(y2 - y1, 0.1f);
        float bin_w = roi_w / (float)Pn;
        float bin_h = roi_h / (float)Pn;
        float sub_w = bin_w / (float)Sn;
        float sub_h = bin_h / (float)Sn;

        float tx = 0.f, tyv = 0.f;
        if (TRANS) {
            tx  = trans[n*98 +      ph*7 + pw] * TRANS_STD;
            tyv = trans[n*98 + 49 + ph*7 + pw] * TRANS_STD;
        }
        float wv = (float)pw * bin_w + x1 + tx  * roi_w + (float)iw * sub_w;
        float hv = (float)ph * bin_h + y1 + tyv * roi_h + (float)ih * sub_h;

        int4   o4 = make_int4(0, 0, 0, 0);
        float4 w4 = make_float4(0.f, 0.f, 0.f, 0.f);
        bool valid = !(wv < -0.5f || wv > (float)Ww - 0.5f ||
                       hv < -0.5f || hv > (float)Hh - 0.5f);
        if (valid) {
            float wc = fminf(fmaxf(wv, 0.f), (float)Ww - 1.f);
            float hc = fminf(fmaxf(hv, 0.f), (float)Hh - 1.f);
            int x0 = (int)floorf(wc);
            int y0 = (int)floorf(hc);
            int x1i = min(x0 + 1, Ww - 1);
            int y1i = min(y0 + 1, Hh - 1);
            float lx = wc - (float)x0;
            float ly = hc - (float)y0;
            o4.x = (y0 * Ww + x0) * Cc;
            o4.y = (x1i - x0) * Cc;
            o4.z = (y1i - y0) * Ww * Cc;
            w4 = make_float4((1.f-ly)*(1.f-lx), (1.f-ly)*lx, ly*(1.f-lx), ly*lx);
            atomicAdd(&s_cnt[pw], 1);
        }
        s_o[tid] = o4;
        s_w[tid] = w4;
        if (tid == 0) s_base = bi * HW * Cc;
    }
    __syncthreads();

    int wid = tid >> 5;
    int l   = tid & 31;
    const float* base = g_dataT + s_base;
    int c4 = l * 4;

    #pragma unroll
    for (int pp = 0; pp < 2; pp++) {
        int pw = wid + pp * 4;
        if (pw >= Pn) break;
        float4 acc = make_float4(0.f, 0.f, 0.f, 0.f);
        #pragma unroll 4
        for (int s = 0; s < 16; s++) {
            int4   o = s_o[pw*16 + s];
            float4 w = s_w[pw*16 + s];
            const float* p = base + o.x + c4;
            float4 v00 = *(const float4*)(p);
            float4 v01 = *(const float4*)(p + o.y);
            float4 v10 = *(const float4*)(p + o.z);
            float4 v11 = *(const float4*)(p + o.y + o.z);
            acc.x += v00.x*w.x + v01.x*w.y + v10.x*w.z + v11.x*w.w;
            acc.y += v00.y*w.x + v01.y*w.y + v10.y*w.z + v11.y*w.w;
            acc.z += v00.z*w.x + v01.z*w.y + v10.z*w.z + v11.z*w.w;
            acc.w += v00.w*w.x + v01.w*w.y + v10.w*w.z + v11.w*w.w;
        }
        int cnt = s_cnt[pw];
        float a[4] = {acc.x, acc.y, acc.z, acc.w};
        float mk = TRANS ? mask[n*49 + ph*7 + pw] : 0.f;
        #pragma unroll
        for (int j = 0; j < 4; j++) {
            float res = (cnt > 0) ? a[j] / (float)cnt : 0.f;
            int oidx = n*INF + (c4 + j)*49 + ph*7 + pw;
            if (TRANS) {
                out[oidx] = res * mk;
            } else {
                __nv_bfloat16 hi = __float2bfloat16(res);
                g_xh[oidx] = hi;
                g_xl[oidx] = __float2bfloat16(res - __bfloat162float(hi));
            }
        }
    }
}

// ---------------- WMMA bf16 GEMM, cp.async 2-stage, KS=64 (col-major B) ---------
// C_tile[128x128] = A[128 x Kper] @ Bt[128 x Kper]^T  (Bt rows are output cols)
// grid: x = Ntiles, y = Mtiles, z = term*kchunks + kc
//   term 0: Ah@Bh   term 1: Ah@Bl   term 2: Al@Bh
#define KS 64
#define SPAD 72
#define NSTG 2
#define STG_ELEMS (2 * 128 * SPAD)     // A + B per stage (bf16 elems)
__global__ __launch_bounds__(256) void gemm_wmma(
    const __nv_bfloat16* __restrict__ Ah, const __nv_bfloat16* __restrict__ Al, int lda,
    const __nv_bfloat16* __restrict__ Bh, const __nv_bfloat16* __restrict__ Bl, int ldb,
    float* __restrict__ part, int Kper, int kchunks, int Nfull)
{
    extern __shared__ __nv_bfloat16 smem[];

    int tid = threadIdx.x;
    int wid = tid >> 5;
    int wm = wid & 3;       // 0..3 : M position (32 rows each)
    int wn = wid >> 2;      // 0..1 : N position (64 cols each)

    int z = blockIdx.z;
    int term = z / kchunks;
    int kc   = z % kchunks;
    const __nv_bfloat16* A = (term == 2) ? Al : Ah;
    const __nv_bfloat16* B = (term == 1) ? Bl : Bh;

    int m0 = blockIdx.y * 128;
    int n0 = blockIdx.x * 128;
    const __nv_bfloat16* Abase = A + (size_t)m0 * lda + (size_t)kc * Kper;
    const __nv_bfloat16* Bbase = B + (size_t)n0 * ldb + (size_t)kc * Kper;

    wmma::fragment<wmma::accumulator, 16, 16, 16, float> acc[2][4];
    #pragma unroll
    for (int i = 0; i < 2; i++)
        #pragma unroll
        for (int j = 0; j < 4; j++) wmma::fill_fragment(acc[i][j], 0.0f);

    int stages = Kper / KS;
    int r  = tid >> 3;       // row group
    int ch = tid & 7;        // 16B chunk within 128B row

    auto issue = [&](int s) {
        int buf = s % NSTG;
        __nv_bfloat16* dA = smem + buf * STG_ELEMS;
        __nv_bfloat16* dB = dA + 128 * SPAD;
        const __nv_bfloat16* a = Abase + s * KS;
        const __nv_bfloat16* b = Bbase + s * KS;
        #pragma unroll
        for (int i = 0; i < 4; i++) {
            int rr = i * 32 + r;
            uint32_t da = smem_u32(dA + rr * SPAD + ch * 8);
            asm volatile("cp.async.cg.shared.global [%0], [%1], 16;"
                         :: "r"(da), "l"(a + (size_t)rr * lda + ch * 8));
            uint32_t db = smem_u32(dB + rr * SPAD + ch * 8);
            asm volatile("cp.async.cg.shared.global [%0], [%1], 16;"
                         :: "r"(db), "l"(b + (size_t)rr * ldb + ch * 8));
        }
        asm volatile("cp.async.commit_group;");
    };

    #pragma unroll
    for (int i = 0; i < NSTG - 1; i++) {
        if (i < stages) issue(i);
        else asm volatile("cp.async.commit_group;");
    }

    for (int s = 0; s < stages; s++) {
        if (s + NSTG - 1 < stages) issue(s + NSTG - 1);
        else asm volatile("cp.async.commit_group;");

        asm volatile("cp.async.wait_group %0;" :: "n"(NSTG - 1));
        __syncthreads();

        int buf = s % NSTG;
        const __nv_bfloat16* cA = smem + buf * STG_ELEMS;
        const __nv_bfloat16* cB = cA + 128 * SPAD;
        #pragma unroll
        for (int kk = 0; kk < KS; kk += 16) {
            wmma::fragment<wmma::matrix_a, 16, 16, 16, __nv_bfloat16, wmma::row_major> af[2];
            wmma::fragment<wmma::matrix_b, 16, 16, 16, __nv_bfloat16, wmma::col_major> bfr[4];
            #pragma unroll
            for (int i = 0; i < 2; i++)
                wmma::load_matrix_sync(af[i], cA + (wm * 32 + i * 16) * SPAD + kk, SPAD);
            #pragma unroll
            for (int j = 0; j < 4; j++)
                wmma::load_matrix_sync(bfr[j], cB + (wn * 64 + j * 16) * SPAD + kk, SPAD);
            #pragma unroll
            for (int i = 0; i < 2; i++)
                #pragma unroll
                for (int j = 0; j < 4; j++)
                    wmma::mma_sync(acc[i][j], af[i], bfr[j], acc[i][j]);
        }
        __syncthreads();
    }

    float* outp = part + ((size_t)z * Nroi + m0) * Nfull + n0;
    #pragma unroll
    for (int i = 0; i < 2; i++)
        #pragma unroll
        for (int j = 0; j < 4; j++)
            wmma::store_matrix_sync(outp + (size_t)(wm * 32 + i * 16) * Nfull + wn * 64 + j * 16,
                                    acc[i][j], Nfull, wmma::mem_row_major);
}

// ---------------- reduce 1: sum 21 slices [256][2048]; split h (bf16 hi/lo) / m (fp32)
__global__ void reduce1_kernel(const float* __restrict__ b1, const float* __restrict__ bm1) {
    int i = blockIdx.x * 256 + threadIdx.x;   // over 256*2048
    int m = i >> 11;
    int n = i & 2047;
    float s = (n < DF) ? b1[n] : bm1[n - DF];
    #pragma unroll
    for (int zz = 0; zz < 21; zz++) s += g_part[(size_t)zz * (Nroi*2*DF) + i];
    s = fmaxf(s, 0.f);
    if (n < DF) {
        __nv_bfloat16 hi = __float2bfloat16(s);
        g_h1h[m*DF + n] = hi;
        g_h1l[m*DF + n] = __float2bfloat16(s - __bfloat162float(hi));
    } else {
        g_m1[m*DF + n - DF] = s;
    }
}

// ---------------- reduce 2: sum 24 slices [256][1024] + b2, relu -> h2 fp32
__global__ void reduce2_kernel(const float* __restrict__ b2) {
    int i = blockIdx.x * 256 + threadIdx.x;
    int n = i & (DF - 1);
    float s = b2[n];
    #pragma unroll
    for (int zz = 0; zz < 24; zz++) s += g_part[(size_t)zz * (Nroi*DF) + i];
    g_h2[i] = fmaxf(s, 0.f);
}

// ---------------- small GEMM: (256,1024) @ (1024,Ncols) + bias [, sigmoid] -------
__global__ __launch_bounds__(128) void gemm_small(
    const float* __restrict__ A, const float* __restrict__ Wt,
    const float* __restrict__ bias, float* __restrict__ out,
    int Ncols, int act)
{
    __shared__ float arow[8][DF];
    int tid = threadIdx.x;
    int m0 = blockIdx.x * 8;
    #pragma unroll
    for (int g = 0; g < 8; g++)
        for (int k = tid; k < DF; k += 128)
            arow[g][k] = A[(size_t)(m0 + g) * DF + k];
    __syncthreads();

    if (tid < Ncols) {
        float bv = bias[tid];
        float acc[8];
        #pragma unroll
        for (int g = 0; g < 8; g++) acc[g] = bv;
        for (int k = 0; k < DF; k += 4) {
            float w0 = Wt[(size_t)(k + 0) * Ncols + tid];
            float w1 = Wt[(size_t)(k + 1) * Ncols + tid];
            float w2 = Wt[(size_t)(k + 2) * Ncols + tid];
            float w3 = Wt[(size_t)(k + 3) * Ncols + tid];
            #pragma unroll
            for (int g = 0; g < 8; g++) {
                float4 av = *(const float4*)&arow[g][k];
                acc[g] += av.x * w0 + av.y * w1 + av.z * w2 + av.w * w3;
            }
        }
        #pragma unroll
        for (int g = 0; g < 8; g++) {
            float v = acc[g];
            if (act) v = 1.f / (1.f + expf(-v));
            out[(size_t)(m0 + g) * Ncols + tid] = v;
        }
    }
}

// ---------------- launch ----------------
extern "C" void kernel_launch(void* const* d_in, const int* in_sizes, int n_in,
                              void* d_out, int out_size) {
    const float* data = (const float*)d_in[0];
    const float* rois = (const float*)d_in[1];
    const float* w1   = (const float*)d_in[2];
    const float* b1   = (const float*)d_in[3];
    const float* w2   = (const float*)d_in[4];
    const float* b2   = (const float*)d_in[5];
    const float* w3   = (const float*)d_in[6];
    const float* b3   = (const float*)d_in[7];
    const float* wm1  = (const float*)d_in[8];
    const float* bm1  = (const float*)d_in[9];
    const float* wm2  = (const float*)d_in[10];
    const float* bm2  = (const float*)d_in[11];
    float* out = (float*)d_out;

    float *p_part, *p_m1, *p_h2, *p_off, *p_mask;
    __nv_bfloat16 *p_xh, *p_xl, *p_W1h, *p_W1l, *p_W2h, *p_W2l, *p_h1h, *p_h1l;
    cudaGetSymbolAddress((void**)&p_part, g_part);
    cudaGetSymbolAddress((void**)&p_m1,   g_m1);
    cudaGetSymbolAddress((void**)&p_h2,   g_h2);
    cudaGetSymbolAddress((void**)&p_off,  g_off);
    cudaGetSymbolAddress((void**)&p_mask, g_mask);
    cudaGetSymbolAddress((void**)&p_xh,   g_xh);
    cudaGetSymbolAddress((void**)&p_xl,   g_xl);
    cudaGetSymbolAddress((void**)&p_W1h,  g_Wt1h);
    cudaGetSymbolAddress((void**)&p_W1l,  g_Wt1l);
    cudaGetSymbolAddress((void**)&p_W2h,  g_Wt2h);
    cudaGetSymbolAddress((void**)&p_W2l,  g_Wt2l);
    cudaGetSymbolAddress((void**)&p_h1h,  g_h1h);
    cudaGetSymbolAddress((void**)&p_h1l,  g_h1l);

    static int attr_set = 0;
    if (!attr_set) {
        cudaFuncSetAttribute(gemm_wmma, cudaFuncAttributeMaxDynamicSharedMemorySize,
                             NSTG * STG_ELEMS * 2);
        attr_set = 1;
    }
    const int smem_bytes = NSTG * STG_ELEMS * 2;   // 73728

    // idx 0: transpose data to channel-last
    transpose_kernel<<<dim3(HW/32, Cc/32, Bb), dim3(32, 8)>>>(data);

    // idx 1: weight transpose + split for w2
    transW_kernel<<<dim3(DF/32, DF/32, 1), 256>>>(w2, nullptr, p_W2h, p_W2l, DF, 0);

    // idx 2: pool1 -> xh/xl bf16
    pool_kernel<false><<<dim3(Nroi, Pn), 128>>>(rois, nullptr, nullptr, nullptr);

    // idx 3 (ncu capture slot): weight transpose + split for w1 & wm1 (merged)
    transW_kernel<<<dim3(INF/32, DF/32, 2), 256>>>(w1, wm1, p_W1h, p_W1l, INF, 1);

    // idx 4: gemm1 [256x6272]@[6272x2048], 3 terms x splitK7 -> 21 slices, 672 CTAs
    gemm_wmma<<<dim3(16, 2, 21), 256, smem_bytes>>>(p_xh, p_xl, INF, p_W1h, p_W1l, INF,
                                                    p_part, INF/7, 7, 2*DF);

    // idx 5: reduce -> h1 (bf16 hi/lo) and m1 (fp32)
    reduce1_kernel<<<(Nroi*2*DF)/256, 256>>>(b1, bm1);

    // idx 6: gemm2 [256x1024]@[1024x1024], 3 terms x splitK8 -> 24 slices, 384 CTAs
    gemm_wmma<<<dim3(8, 2, 24), 256, smem_bytes>>>(p_h1h, p_h1l, DF, p_W2h, p_W2l, DF,
                                                   p_part, DF/8, 8, DF);

    // idx 7: reduce -> h2 fp32
    reduce2_kernel<<<(Nroi*DF)/256, 256>>>(b2);

    // idx 8/9: offsets & mask heads
    gemm_small<<<Nroi/8, 128>>>(p_h2, w3, b3, p_off, 2*Pn*Pn, 0);
    gemm_small<<<Nroi/8, 128>>>(p_m1, wm2, bm2, p_mask, Pn*Pn, 1);

    // idx 10: pool2 with offsets, multiply mask -> out
    pool_kernel<true><<<dim3(Nroi, Pn), 128>>>(rois, p_off, p_mask, out);
}

// round 17
// speedup vs baseline: 1.0794x; 1.0329x over previous
#include <cuda_runtime.h>
#include <cuda_bf16.h>
#include <mma.h>
#include <math.h>
#include <stdint.h>

using namespace nvcuda;

#define Pn 7
#define Sn 4
#define SCALE 0.0625f
#define TRANS_STD 0.1f
#define Cc 128
#define DF 1024
#define Bb 2
#define Hh 160
#define Ww 160
#define Nroi 256
#define INF (Cc*Pn*Pn)   // 6272
#define HW (Hh*Ww)       // 25600

// ---------------- scratch ----------------
__device__ float g_dataT[Bb*HW*Cc];                 // (B,H,W,C)
__device__ __align__(16) __nv_bfloat16 g_xh[Nroi*INF];
__device__ __align__(16) __nv_bfloat16 g_xl[Nroi*INF];
__device__ __align__(16) __nv_bfloat16 g_Wt1h[2*DF*INF];   // [2048][6272] = w1^T | wm1^T (hi)
__device__ __align__(16) __nv_bfloat16 g_Wt1l[2*DF*INF];   // lo
__device__ __align__(16) __nv_bfloat16 g_Wt2h[DF*DF];      // w2^T hi
__device__ __align__(16) __nv_bfloat16 g_Wt2l[DF*DF];      // w2^T lo
__device__ float g_part[11010048];                  // partials (21*256*2048)
__device__ __align__(16) __nv_bfloat16 g_h1h[Nroi*DF];
__device__ __align__(16) __nv_bfloat16 g_h1l[Nroi*DF];
__device__ float g_m1[Nroi*DF];
__device__ float g_h2[Nroi*DF];
__device__ float g_off[Nroi*2*Pn*Pn];
__device__ float g_mask[Nroi*Pn*Pn];

__device__ __forceinline__ uint32_t smem_u32(const void* p) {
    uint32_t a;
    asm("{ .reg .u64 t; cvta.to.shared.u64 t, %1; cvt.u32.u64 %0, t; }" : "=r"(a) : "l"(p));
    return a;
}

// ---------------- transpose (B,C,H,W) -> (B,H,W,C) ----------------
__global__ void transpose_kernel(const float* __restrict__ in) {
    __shared__ float tile[32][33];
    int b  = blockIdx.z;
    int p0 = blockIdx.x * 32;
    int c0 = blockIdx.y * 32;
    int tx = threadIdx.x, ty = threadIdx.y;
    const float* src = in + (size_t)b * Cc * HW;
    float* dst = g_dataT + (size_t)b * HW * Cc;
    #pragma unroll
    for (int i = 0; i < 4; i++)
        tile[ty + 8*i][tx] = src[(c0 + ty + 8*i) * HW + p0 + tx];
    __syncthreads();
    #pragma unroll
    for (int i = 0; i < 4; i++)
        dst[(p0 + ty + 8*i) * Cc + c0 + tx] = tile[tx][ty + 8*i];
}

// ---------------- weight transpose + bf16 hi/lo split (vectorized stores) -------
__global__ __launch_bounds__(256) void transW_kernel(
    const float* __restrict__ w_a, const float* __restrict__ w_b,
    __nv_bfloat16* __restrict__ Wth, __nv_bfloat16* __restrict__ Wtl,
    int ldt, int two)
{
    __shared__ float tile[32][33];   // [k_local][n_local]
    const float* w = (two && blockIdx.z) ? w_b : w_a;
    int nOff = (two && blockIdx.z) ? DF : 0;
    int k0 = blockIdx.x * 32;
    int n0 = blockIdx.y * 32;
    int tid = threadIdx.x;
    int lk = tid >> 5;       // 0..7
    int ln = tid & 31;
    #pragma unroll
    for (int i = 0; i < 4; i++)
        tile[lk + 8*i][ln] = w[(size_t)(k0 + lk + 8*i) * DF + n0 + ln];
    __syncthreads();

    int nl = tid >> 3;       // 0..31 output row within tile
    int kc = tid & 7;        // 0..7, covers k-offsets kc*4..kc*4+3
    float v0 = tile[kc*4+0][nl];
    float v1 = tile[kc*4+1][nl];
    float v2 = tile[kc*4+2][nl];
    float v3 = tile[kc*4+3][nl];
    __nv_bfloat16 h0 = __float2bfloat16(v0);
    __nv_bfloat16 h1 = __float2bfloat16(v1);
    __nv_bfloat16 h2 = __float2bfloat16(v2);
    __nv_bfloat16 h3 = __float2bfloat16(v3);
    __nv_bfloat16 l0 = __float2bfloat16(v0 - __bfloat162float(h0));
    __nv_bfloat16 l1 = __float2bfloat16(v1 - __bfloat162float(h1));
    __nv_bfloat16 l2 = __float2bfloat16(v2 - __bfloat162float(h2));
    __nv_bfloat16 l3 = __float2bfloat16(v3 - __bfloat162float(h3));
    size_t o = (size_t)(nOff + n0 + nl) * ldt + k0 + kc * 4;
    __nv_bfloat162 ha; ha.x = h0; ha.y = h1;
    __nv_bfloat162 hb; hb.x = h2; hb.y = h3;
    __nv_bfloat162 la; la.x = l0; la.y = l1;
    __nv_bfloat162 lb; lb.x = l2; lb.y = l3;
    ((__nv_bfloat162*)(Wth + o))[0] = ha;
    ((__nv_bfloat162*)(Wth + o))[1] = hb;
    ((__nv_bfloat162*)(Wtl + o))[0] = la;
    ((__nv_bfloat162*)(Wtl + o))[1] = lb;
}

// ---------------- deformable RoI pool (texel-dedup two-phase) ----------------
// grid (Nroi, Pn), 128 threads.
// Phase 1a: threads 0..111 compute per-sample (y0,x0,dy1,dx1,valid) + 4 weights.
// Phase 1b: thread b (<7) accumulates its bin's 64 corner weights into a 6x6
//           texel weight grid (deterministic order, no atomics).
// Phase 2: warp w handles pw {w, w+4}; lane l -> channels 4l..4l+3; one float4
//          gather per nonzero grid cell.
template<bool TRANS>
__global__ __launch_bounds__(128) void pool_kernel(
    const float* __restrict__ rois,
    const float* __restrict__ trans,
    const float* __restrict__ mask,
    float* __restrict__ out)
{
    __shared__ float  s_grid[Pn][36];
    __shared__ float4 s_w[Pn*16];
    __shared__ int    s_pack[Pn*16];
    __shared__ int    s_org[Pn];
    __shared__ int    s_cnt[Pn];
    __shared__ int    s_base;

    int n  = blockIdx.x;
    int ph = blockIdx.y;
    int tid = threadIdx.x;

    for (int i = tid; i < Pn*36; i += 128) ((float*)s_grid)[i] = 0.f;
    __syncthreads();

    if (tid < Pn * 16) {
        int pw = tid >> 4;
        int s  = tid & 15;
        int ih = s >> 2;
        int iw = s & 3;

        const float* r = rois + n * 5;
        int   bi = (int)r[0];
        float x1 = rintf(r[1]) * SCALE - 0.5f;
        float y1 = rintf(r[2]) * SCALE - 0.5f;
        float x2 = (rintf(r[3]) + 1.0f) * SCALE - 0.5f;
        float y2 = (rintf(r[4]) + 1.0f) * SCALE - 0.5f;
        float roi_w = fmaxf(x2 - x1, 0.1f);
        float roi_h = fmaxf(y2 - y1, 0.1f);
        float bin_w = roi_w / (float)Pn;
        float bin_h = roi_h / (float)Pn;
        float sub_w = bin_w / (float)Sn;
        float sub_h = bin_h / (float)Sn;

        float tx = 0.f, tyv = 0.f;
        if (TRANS) {
            tx  = trans[n*98 +      ph*7 + pw] * TRANS_STD;
            tyv = trans[n*98 + 49 + ph*7 + pw] * TRANS_STD;
        }
        float wv = (float)pw * bin_w + x1 + tx  * roi_w + (float)iw * sub_w;
        float hv = (float)ph * bin_h + y1 + tyv * roi_h + (float)ih * sub_h;

        bool valid = !(wv < -0.5f || wv > (float)Ww - 0.5f ||
                       hv < -0.5f || hv > (float)Hh - 0.5f);
        float wc = fminf(fmaxf(wv, 0.f), (float)Ww - 1.f);
        float hc = fminf(fmaxf(hv, 0.f), (float)Hh - 1.f);
        int x0 = (int)floorf(wc);
        int y0 = (int)floorf(hc);
        int x1i = min(x0 + 1, Ww - 1);
        int y1i = min(y0 + 1, Hh - 1);
        float lx = wc - (float)x0;
        float ly = hc - (float)y0;
        s_w[tid] = make_float4((1.f-ly)*(1.f-lx), (1.f-ly)*lx, ly*(1.f-lx), ly*lx);
        s_pack[tid] = y0 | (x0 << 8) | ((y1i - y0) << 16) | ((x1i - x0) << 17)
                    | ((valid ? 1 : 0) << 18);
        if (tid == 0) s_base = bi * HW * Cc;
    }
    __syncthreads();

    // Phase 1b: per-bin deterministic weight-grid accumulation
    if (tid < Pn) {
        int b = tid;
        int p0 = s_pack[b * 16];
        int yorg = p0 & 255;
        int xorg = (p0 >> 8) & 255;
        int cnt = 0;
        #pragma unroll
        for (int s = 0; s < 16; s++) {
            int pk = s_pack[b * 16 + s];
            if (!((pk >> 18) & 1)) continue;
            cnt++;
            float4 w = s_w[b * 16 + s];
            int dy  = (pk & 255) - yorg;
            int dx  = ((pk >> 8) & 255) - xorg;
            int dy1 = dy + ((pk >> 16) & 1);
            int dx1 = dx + ((pk >> 17) & 1);
            s_grid[b][dy  * 6 + dx ] += w.x;
            s_grid[b][dy  * 6 + dx1] += w.y;
            s_grid[b][dy1 * 6 + dx ] += w.z;
            s_grid[b][dy1 * 6 + dx1] += w.w;
        }
        s_cnt[b] = cnt;
        s_org[b] = yorg * Ww + xorg;
    }
    __syncthreads();

    int wid = tid >> 5;
    int l   = tid & 31;
    const float* base = g_dataT + s_base;
    int c4 = l * 4;

    #pragma unroll
    for (int pp = 0; pp < 2; pp++) {
        int pw = wid + pp * 4;
        if (pw >= Pn) break;
        const float* bb = base + s_org[pw] * Cc + c4;
        float4 acc = make_float4(0.f, 0.f, 0.f, 0.f);
        #pragma unroll
        for (int cell = 0; cell < 36; cell++) {
            float wgt = s_grid[pw][cell];
            if (wgt != 0.f) {
                const int dy = cell / 6, dx = cell % 6;
                float4 v = *(const float4*)(bb + (dy * Ww + dx) * Cc);
                acc.x += wgt * v.x;
                acc.y += wgt * v.y;
                acc.z += wgt * v.z;
                acc.w += wgt * v.w;
            }
        }
        int cnt = s_cnt[pw];
        float a[4] = {acc.x, acc.y, acc.z, acc.w};
        float mk = TRANS ? mask[n*49 + ph*7 + pw] : 0.f;
        #pragma unroll
        for (int j = 0; j < 4; j++) {
            float res = (cnt > 0) ? a[j] / (float)cnt : 0.f;
            int oidx = n*INF + (c4 + j)*49 + ph*7 + pw;
            if (TRANS) {
                out[oidx] = res * mk;
            } else {
                __nv_bfloat16 hi = __float2bfloat16(res);
                g_xh[oidx] = hi;
                g_xl[oidx] = __float2bfloat16(res - __bfloat162float(hi));
            }
        }
    }
}

// ---------------- WMMA bf16 GEMM, cp.async 2-stage, KS=64 (col-major B) ---------
#define KS 64
#define SPAD 72
#define NSTG 2
#define STG_ELEMS (2 * 128 * SPAD)     // A + B per stage (bf16 elems)
__global__ __launch_bounds__(256) void gemm_wmma(
    const __nv_bfloat16* __restrict__ Ah, const __nv_bfloat16* __restrict__ Al, int lda,
    const __nv_bfloat16* __restrict__ Bh, const __nv_bfloat16* __restrict__ Bl, int ldb,
    float* __restrict__ part, int Kper, int kchunks, int Nfull)
{
    extern __shared__ __nv_bfloat16 smem[];

    int tid = threadIdx.x;
    int wid = tid >> 5;
    int wm = wid & 3;       // 0..3 : M position (32 rows each)
    int wn = wid >> 2;      // 0..1 : N position (64 cols each)

    int z = blockIdx.z;
    int term = z / kchunks;
    int kc   = z % kchunks;
    const __nv_bfloat16* A = (term == 2) ? Al : Ah;
    const __nv_bfloat16* B = (term == 1) ? Bl : Bh;

    int m0 = blockIdx.y * 128;
    int n0 = blockIdx.x * 128;
    const __nv_bfloat16* Abase = A + (size_t)m0 * lda + (size_t)kc * Kper;
    const __nv_bfloat16* Bbase = B + (size_t)n0 * ldb + (size_t)kc * Kper;

    wmma::fragment<wmma::accumulator, 16, 16, 16, float> acc[2][4];
    #pragma unroll
    for (int i = 0; i < 2; i++)
        #pragma unroll
        for (int j = 0; j < 4; j++) wmma::fill_fragment(acc[i][j], 0.0f);

    int stages = Kper / KS;
    int r  = tid >> 3;       // row group
    int ch = tid & 7;        // 16B chunk within 128B row

    auto issue = [&](int s) {
        int buf = s % NSTG;
        __nv_bfloat16* dA = smem + buf * STG_ELEMS;
        __nv_bfloat16* dB = dA + 128 * SPAD;
        const __nv_bfloat16* a = Abase + s * KS;
        const __nv_bfloat16* b = Bbase + s * KS;
        #pragma unroll
        for (int i = 0; i < 4; i++) {
            int rr = i * 32 + r;
            uint32_t da = smem_u32(dA + rr * SPAD + ch * 8);
            asm volatile("cp.async.cg.shared.global [%0], [%1], 16;"
                         :: "r"(da), "l"(a + (size_t)rr * lda + ch * 8));
            uint32_t db = smem_u32(dB + rr * SPAD + ch * 8);
            asm volatile("cp.async.cg.shared.global [%0], [%1], 16;"
                         :: "r"(db), "l"(b + (size_t)rr * ldb + ch * 8));
        }
        asm volatile("cp.async.commit_group;");
    };

    #pragma unroll
    for (int i = 0; i < NSTG - 1; i++) {
        if (i < stages) issue(i);
        else asm volatile("cp.async.commit_group;");
    }

    for (int s = 0; s < stages; s++) {
        if (s + NSTG - 1 < stages) issue(s + NSTG - 1);
        else asm volatile("cp.async.commit_group;");

        asm volatile("cp.async.wait_group %0;" :: "n"(NSTG - 1));
        __syncthreads();

        int buf = s % NSTG;
        const __nv_bfloat16* cA = smem + buf * STG_ELEMS;
        const __nv_bfloat16* cB = cA + 128 * SPAD;
        #pragma unroll
        for (int kk = 0; kk < KS; kk += 16) {
            wmma::fragment<wmma::matrix_a, 16, 16, 16, __nv_bfloat16, wmma::row_major> af[2];
            wmma::fragment<wmma::matrix_b, 16, 16, 16, __nv_bfloat16, wmma::col_major> bfr[4];
            #pragma unroll
            for (int i = 0; i < 2; i++)
                wmma::load_matrix_sync(af[i], cA + (wm * 32 + i * 16) * SPAD + kk, SPAD);
            #pragma unroll
            for (int j = 0; j < 4; j++)
                wmma::load_matrix_sync(bfr[j], cB + (wn * 64 + j * 16) * SPAD + kk, SPAD);
            #pragma unroll
            for (int i = 0; i < 2; i++)
                #pragma unroll
                for (int j = 0; j < 4; j++)
                    wmma::mma_sync(acc[i][j], af[i], bfr[j], acc[i][j]);
        }
        __syncthreads();
    }

    float* outp = part + ((size_t)z * Nroi + m0) * Nfull + n0;
    #pragma unroll
    for (int i = 0; i < 2; i++)
        #pragma unroll
        for (int j = 0; j < 4; j++)
            wmma::store_matrix_sync(outp + (size_t)(wm * 32 + i * 16) * Nfull + wn * 64 + j * 16,
                                    acc[i][j], Nfull, wmma::mem_row_major);
}

// ---------------- reduce 1: sum 21 slices [256][2048]; split h (bf16 hi/lo) / m (fp32)
__global__ void reduce1_kernel(const float* __restrict__ b1, const float* __restrict__ bm1) {
    int i = blockIdx.x * 256 + threadIdx.x;   // over 256*2048
    int m = i >> 11;
    int n = i & 2047;
    float s = (n < DF) ? b1[n] : bm1[n - DF];
    #pragma unroll
    for (int zz = 0; zz < 21; zz++) s += g_part[(size_t)zz * (Nroi*2*DF) + i];
    s = fmaxf(s, 0.f);
    if (n < DF) {
        __nv_bfloat16 hi = __float2bfloat16(s);
        g_h1h[m*DF + n] = hi;
        g_h1l[m*DF + n] = __float2bfloat16(s - __bfloat162float(hi));
    } else {
        g_m1[m*DF + n - DF] = s;
    }
}

// ---------------- reduce 2: sum 24 slices [256][1024] + b2, relu -> h2 fp32
__global__ void reduce2_kernel(const float* __restrict__ b2) {
    int i = blockIdx.x * 256 + threadIdx.x;
    int n = i & (DF - 1);
    float s = b2[n];
    #pragma unroll
    for (int zz = 0; zz < 24; zz++) s += g_part[(size_t)zz * (Nroi*DF) + i];
    g_h2[i] = fmaxf(s, 0.f);
}

// ---------------- small GEMM: (256,1024) @ (1024,Ncols) + bias [, sigmoid] -------
__global__ __launch_bounds__(128) void gemm_small(
    const float* __restrict__ A, const float* __restrict__ Wt,
    const float* __restrict__ bias, float* __restrict__ out,
    int Ncols, int act)
{
    __shared__ float arow[8][DF];
    int tid = threadIdx.x;
    int m0 = blockIdx.x * 8;
    #pragma unroll
    for (int g = 0; g < 8; g++)
        for (int k = tid; k < DF; k += 128)
            arow[g][k] = A[(size_t)(m0 + g) * DF + k];
    __syncthreads();

    if (tid < Ncols) {
        float bv = bias[tid];
        float acc[8];
        #pragma unroll
        for (int g = 0; g < 8; g++) acc[g] = bv;
        for (int k = 0; k < DF; k += 4) {
            float w0 = Wt[(size_t)(k + 0) * Ncols + tid];
            float w1 = Wt[(size_t)(k + 1) * Ncols + tid];
            float w2 = Wt[(size_t)(k + 2) * Ncols + tid];
            float w3 = Wt[(size_t)(k + 3) * Ncols + tid];
            #pragma unroll
            for (int g = 0; g < 8; g++) {
                float4 av = *(const float4*)&arow[g][k];
                acc[g] += av.x * w0 + av.y * w1 + av.z * w2 + av.w * w3;
            }
        }
        #pragma unroll
        for (int g = 0; g < 8; g++) {
            float v = acc[g];
            if (act) v = 1.f / (1.f + expf(-v));
            out[(size_t)(m0 + g) * Ncols + tid] = v;
        }
    }
}

// ---------------- launch ----------------
extern "C" void kernel_launch(void* const* d_in, const int* in_sizes, int n_in,
                              void* d_out, int out_size) {
    const float* data = (const float*)d_in[0];
    const float* rois = (const float*)d_in[1];
    const float* w1   = (const float*)d_in[2];
    const float* b1   = (const float*)d_in[3];
    const float* w2   = (const float*)d_in[4];
    const float* b2   = (const float*)d_in[5];
    const float* w3   = (const float*)d_in[6];
    const float* b3   = (const float*)d_in[7];
    const float* wm1  = (const float*)d_in[8];
    const float* bm1  = (const float*)d_in[9];
    const float* wm2  = (const float*)d_in[10];
    const float* bm2  = (const float*)d_in[11];
    float* out = (float*)d_out;

    float *p_part, *p_m1, *p_h2, *p_off, *p_mask;
    __nv_bfloat16 *p_xh, *p_xl, *p_W1h, *p_W1l, *p_W2h, *p_W2l, *p_h1h, *p_h1l;
    cudaGetSymbolAddress((void**)&p_part, g_part);
    cudaGetSymbolAddress((void**)&p_m1,   g_m1);
    cudaGetSymbolAddress((void**)&p_h2,   g_h2);
    cudaGetSymbolAddress((void**)&p_off,  g_off);
    cudaGetSymbolAddress((void**)&p_mask, g_mask);
    cudaGetSymbolAddress((void**)&p_xh,   g_xh);
    cudaGetSymbolAddress((void**)&p_xl,   g_xl);
    cudaGetSymbolAddress((void**)&p_W1h,  g_Wt1h);
    cudaGetSymbolAddress((void**)&p_W1l,  g_Wt1l);
    cudaGetSymbolAddress((void**)&p_W2h,  g_Wt2h);
    cudaGetSymbolAddress((void**)&p_W2l,  g_Wt2l);
    cudaGetSymbolAddress((void**)&p_h1h,  g_h1h);
    cudaGetSymbolAddress((void**)&p_h1l,  g_h1l);

    static int attr_set = 0;
    if (!attr_set) {
        cudaFuncSetAttribute(gemm_wmma, cudaFuncAttributeMaxDynamicSharedMemorySize,
                             NSTG * STG_ELEMS * 2);
        attr_set = 1;
    }
    const int smem_bytes = NSTG * STG_ELEMS * 2;   // 73728

    // idx 0: transpose data to channel-last
    transpose_kernel<<<dim3(HW/32, Cc/32, Bb), dim3(32, 8)>>>(data);

    // idx 1: weight transpose + split for w2
    transW_kernel<<<dim3(DF/32, DF/32, 1), 256>>>(w2, nullptr, p_W2h, p_W2l, DF, 0);

    // idx 2: weight transpose + split for w1 & wm1 (merged)
    transW_kernel<<<dim3(INF/32, DF/32, 2), 256>>>(w1, wm1, p_W1h, p_W1l, INF, 1);

    // idx 3 (ncu capture slot): pool1 -> xh/xl bf16
    pool_kernel<false><<<dim3(Nroi, Pn), 128>>>(rois, nullptr, nullptr, nullptr);

    // idx 4: gemm1 [256x6272]@[6272x2048], 3 terms x splitK7 -> 21 slices, 672 CTAs
    gemm_wmma<<<dim3(16, 2, 21), 256, smem_bytes>>>(p_xh, p_xl, INF, p_W1h, p_W1l, INF,
                                                    p_part, INF/7, 7, 2*DF);

    // idx 5: reduce -> h1 (bf16 hi/lo) and m1 (fp32)
    reduce1_kernel<<<(Nroi*2*DF)/256, 256>>>(b1, bm1);

    // idx 6: gemm2 [256x1024]@[1024x1024], 3 terms x splitK8 -> 24 slices, 384 CTAs
    gemm_wmma<<<dim3(8, 2, 24), 256, smem_bytes>>>(p_h1h, p_h1l, DF, p_W2h, p_W2l, DF,
                                                   p_part, DF/8, 8, DF);

    // idx 7: reduce -> h2 fp32
    reduce2_kernel<<<(Nroi*DF)/256, 256>>>(b2);

    // idx 8/9: offsets & mask heads
    gemm_small<<<Nroi/8, 128>>>(p_h2, w3, b3, p_off, 2*Pn*Pn, 0);
    gemm_small<<<Nroi/8, 128>>>(p_m1, wm2, bm2, p_mask, Pn*Pn, 1);

    // idx 10: pool2 with offsets, multiply mask -> out
    pool_kernel<true><<<dim3(Nroi, Pn), 128>>>(rois, p_off, p_mask, out);
}